// round 14
// baseline (speedup 1.0000x reference)
#include <cuda_runtime.h>
#include <cuda_fp16.h>

#define PH 7
#define PW 7
#define SP 4
#define CH 10
#define FH 34
#define FW 34
#define NPIX (FH * FW)      // 1156
#define NBINS (PH * PW)     // 49
#define NQ (CH * NBINS)     // 490
#define TPB 256
#define RPT 8               // rois per thread
#define RPB (TPB * RPT)     // 2048 rois per block
#define NPAD 10240          // padded roi stride
#define PADC 16             // halves per pixel slot (10 used), 32B stride

// scratch[(c*49+bin)*NPAD + n], fp16, ~10 MB (fully L2-resident)
__device__ __half g_scratch[CH * NBINS * NPAD];
// per-roi separable weights: {g0, g1, g2, rowoff} per (ph|pw, n)
__device__ float4 g_wy[PH * NPAD];
__device__ float4 g_wx[PW * NPAD];

// ---------------------------------------------------------------------------
// Kernel 0: per-roi weight precompute, one thread per (n, p, axis).
// Fast division (roi * 1/7) with an exact-div fallback guarded on the ONLY
// discontinuity: floor(rs + p*bin). Per-sample floors are continuous in the
// bin size (bilinear weights are continuous across pixel crossings), so
// 1-ulp division error there is harmless. Guard margin 1e-4 >> max fast/exact
// divergence (~4e-6) -> floors always match the IEEE reference.
// Branchless SCALAR accumulators (dynamic-index register arrays spill).
// ---------------------------------------------------------------------------
__global__ void __launch_bounds__(TPB) weights_kernel(
    const float* __restrict__ rois, int N)
{
    const int n = blockIdx.x * TPB + threadIdx.x;
    if (n >= N) return;
    const int k = blockIdx.y;                 // 0..13

    const bool isY = (k < PH);
    const int  p   = isY ? k : k - PH;
    const float fp = (float)p;

    const float rs = __ldg(&rois[n * 5 + (isY ? 2 : 1)]) * 0.125f;
    const float re = __ldg(&rois[n * 5 + (isY ? 4 : 3)]) * 0.125f;

    float roi = re - rs; if (!(roi > 0.1f)) roi = 0.1f;

    // Fast path
    float binsz = roi * (1.0f / 7.0f);
    float arg   = __fadd_rn(rs, __fmul_rn(fp, binsz));
    float start = floorf(arg);
    const float frac = arg - start;
    if (frac < 1e-4f || frac > 1.0f - 1e-4f) {
        // Near a bin-start integer boundary: recompute with exact rn division
        // so floor matches the reference bit-exactly.
        binsz = __fdiv_rn(roi, 7.0f);
        arg   = __fadd_rn(rs, __fmul_rn(fp, binsz));
        start = floorf(arg);
    }
    const float subsz = 0.25f * binsz;
    const int v0 = (int)start;

    float g0 = 0.f, g1 = 0.f, g2 = 0.f;
    #pragma unroll
    for (int s = 0; s < SP; ++s) {
        const float P  = __fadd_rn(start, __fmul_rn((float)s + 0.5f, subsz));
        const float pf = floorf(P);
        const float d  = P - pf;
        const int v1 = (int)pf;
        const bool hi = (v1 != v0);             // sample fell in row v0+1
        const float w1 = 1.0f - d;
        const float w2 = (v1 + 1 < FH) ? d : 0.0f;   // FH == FW == 34
        g0 += hi ? 0.0f : w1;
        g1 += hi ? w1   : w2;
        g2 += hi ? w2   : 0.0f;
    }

    if (isY)
        g_wy[p * NPAD + n] = make_float4(g0 * 0.0625f, g1 * 0.0625f,
                                         g2 * 0.0625f, (float)(v0 * FW));
    else
        g_wx[p * NPAD + n] = make_float4(g0, g1, g2, (float)v0);
}

// ---------------------------------------------------------------------------
// Kernel 1: per-bin gather into fp16 scratch (coalesced n-major STG.16).
// Feature staged as fp16 [pix][16 halves] -> 2 LDS per tap. RPT=8 -> 245
// blocks = one resident wave, smem fill traffic halved.
// 2x2 core taps always live; third row/column branch-guarded. Validity
// predicates derived from float compares (no integer division).
// ---------------------------------------------------------------------------
__global__ void __launch_bounds__(TPB) psroi_kernel(
    const float* __restrict__ ft, int N)
{
    __shared__ __align__(16) __half sm[NPIX * PADC];   // 36,992 B

    const int bin = blockIdx.y;
    const int ph  = bin / PW;
    const int pw  = bin - ph * PW;
    const int tid = threadIdx.x;

    // Stage the (ph,pw) slice, all 10 channels, as fp16 [pix][c]
    {
        const float* base = ft + (size_t)bin * NPIX;
        for (int p = tid; p < NPIX; p += TPB) {
            unsigned int h2[5];
            #pragma unroll
            for (int c = 0; c < 5; ++c) {
                float a = base[(size_t)(2 * c)     * (NBINS * NPIX) + p];
                float b = base[(size_t)(2 * c + 1) * (NBINS * NPIX) + p];
                __half2 hh = __floats2half2_rn(a, b);
                h2[c] = *(unsigned int*)&hh;
            }
            uint4* dst = (uint4*)(sm + p * PADC);
            *dst = make_uint4(h2[0], h2[1], h2[2], h2[3]);
            *(unsigned int*)(sm + p * PADC + 8) = h2[4];
        }
    }
    __syncthreads();

    const float4* __restrict__ wyp = g_wy + (size_t)ph * NPAD;
    const float4* __restrict__ wxp = g_wx + (size_t)pw * NPAD;

    const int nbase = blockIdx.x * RPB + tid;

    #pragma unroll 1
    for (int r = 0; r < RPT; ++r) {
        const int n = nbase + r * TPB;
        if (n >= N) break;

        const float4 wy = __ldg(&wyp[n]);
        const float4 wx = __ldg(&wxp[n]);
        const int rowbase = (int)(wy.w + wx.w);   // y0*34 + x0, exact in f32

        float acc[CH];
        #pragma unroll
        for (int c = 0; c < CH; ++c) acc[c] = 0.f;

        auto tap = [&](int pix, float w) {
            const __half* pp = sm + pix * PADC;
            const uint4 v = *(const uint4*)pp;
            const unsigned int v4 = *(const unsigned int*)(pp + 8);
            const float2 f0 = __half22float2(*(const __half2*)&v.x);
            const float2 f1 = __half22float2(*(const __half2*)&v.y);
            const float2 f2 = __half22float2(*(const __half2*)&v.z);
            const float2 f3 = __half22float2(*(const __half2*)&v.w);
            const float2 f4 = __half22float2(*(const __half2*)&v4);
            acc[0] = fmaf(w, f0.x, acc[0]);
            acc[1] = fmaf(w, f0.y, acc[1]);
            acc[2] = fmaf(w, f1.x, acc[2]);
            acc[3] = fmaf(w, f1.y, acc[3]);
            acc[4] = fmaf(w, f2.x, acc[4]);
            acc[5] = fmaf(w, f2.y, acc[5]);
            acc[6] = fmaf(w, f3.x, acc[6]);
            acc[7] = fmaf(w, f3.y, acc[7]);
            acc[8] = fmaf(w, f4.x, acc[8]);
            acc[9] = fmaf(w, f4.y, acc[9]);
        };

        // When y0==33 (x0==33) the row1/col1 weights are provably zero, so
        // clamping keeps the dead read in-bounds. Float compares: y0<33 iff
        // rowoff(y) < 33*34 = 1122; x0<33 directly.
        const int r0 = rowbase;
        const int r1 = r0 + ((wy.w < 1122.0f) ? FW : 0);
        const int c1 = (wx.w < 33.0f) ? 1 : 0;

        // 2x2 core: always live, unconditional -> 8 LDS pipelined.
        tap(r0,      wy.x * wx.x);
        tap(r0 + c1, wy.x * wx.y);
        tap(r1,      wy.y * wx.x);
        tap(r1 + c1, wy.y * wx.y);

        if (wx.z != 0.f) {
            tap(r0 + 2, wy.x * wx.z);
            tap(r1 + 2, wy.y * wx.z);
        }
        if (wy.z != 0.f) {
            const int r2 = r0 + 2 * FW;
            tap(r2,      wy.z * wx.x);
            tap(r2 + c1, wy.z * wx.y);
            if (wx.z != 0.f)
                tap(r2 + 2, wy.z * wx.z);
        }

        __half* sc = g_scratch + (size_t)bin * NPAD + n;
        #pragma unroll
        for (int c = 0; c < CH; ++c)
            sc[(size_t)c * (NBINS * NPAD)] = __float2half_rn(acc[c]);
    }
}

// ---------------------------------------------------------------------------
// Kernel 2: out[n*490 + q] = (float)scratch[q*NPAD + n], q = c*49+bin.
// Single 32q x 128n tile per block (proven best; bank-optimal both phases).
// ---------------------------------------------------------------------------
#define TQ 32
#define TN 128
#define TS 129

__global__ void __launch_bounds__(256) transpose_kernel(
    float* __restrict__ out, int N)
{
    __shared__ float tile[TQ * TS];  // 16.5 KB

    const int tid   = threadIdx.x;
    const int qBase = blockIdx.y * TQ;
    const int nBase = blockIdx.x * TN;

    // Load: lane reads 4 consecutive n as uint2 (8B); warp covers 128 n.
    {
        const int lane = tid & 31;
        const int qrow = tid >> 5;            // 0..7
        #pragma unroll
        for (int qi = 0; qi < 4; ++qi) {
            const int q  = qrow + qi * 8;     // 0..31
            const int qg = qBase + q;
            if (qg < NQ) {
                const uint2 raw = __ldg((const uint2*)
                    (g_scratch + (size_t)qg * NPAD + nBase + lane * 4));
                const float2 a = __half22float2(*(const __half2*)&raw.x);
                const float2 b = __half22float2(*(const __half2*)&raw.y);
                float* t = tile + q * TS + lane * 4;
                t[0] = a.x; t[1] = a.y; t[2] = b.x; t[3] = b.y;
            }
        }
    }
    __syncthreads();

    // Store: half-warp covers a 128B contiguous q-span of one output row.
    {
        const int c2 = tid & 15;              // q pair: qBase + 2*c2
        const int nr = tid >> 4;              // 0..15
        const int q0 = qBase + 2 * c2;
        if (q0 + 1 < NQ) {
            #pragma unroll
            for (int k = 0; k < 8; ++k) {
                const int nl = nr + k * 16;   // 0..127
                const int ng = nBase + nl;
                if (ng < N) {
                    float2 v;
                    v.x = tile[(2 * c2)     * TS + nl];
                    v.y = tile[(2 * c2 + 1) * TS + nl];
                    *(float2*)(out + (size_t)ng * NQ + q0) = v;
                }
            }
        }
    }
}

extern "C" void kernel_launch(void* const* d_in, const int* in_sizes, int n_in,
                              void* d_out, int out_size)
{
    const float* ft   = (const float*)d_in[0];   // 490*34*34 floats
    const float* rois = (const float*)d_in[1];   // N*5 floats
    float* out        = (float*)d_out;           // N*10*49 floats

    const int N = in_sizes[1] / 5;

    dim3 grid0((N + TPB - 1) / TPB, PH + PW);
    weights_kernel<<<grid0, TPB>>>(rois, N);

    dim3 grid1((N + RPB - 1) / RPB, NBINS);
    psroi_kernel<<<grid1, TPB>>>(ft, N);

    dim3 grid2((N + TN - 1) / TN, (NQ + TQ - 1) / TQ);
    transpose_kernel<<<grid2, 256>>>(out, N);
}

// round 15
// speedup vs baseline: 1.0089x; 1.0089x over previous
#include <cuda_runtime.h>
#include <cuda_fp16.h>

#define PH 7
#define PW 7
#define SP 4
#define CH 10
#define FH 34
#define FW 34
#define NPIX (FH * FW)      // 1156
#define NBINS (PH * PW)     // 49
#define NQ (CH * NBINS)     // 490
#define TPB 256
#define RPT 4               // rois per thread
#define RPB (TPB * RPT)     // 1024 rois per block
#define NPAD 10240          // padded roi stride
#define PADC 16             // halves per pixel slot (10 used), 32B stride

// scratch[(c*49+bin)*NPAD + n], fp16, ~10 MB (fully L2-resident)
__device__ __half g_scratch[CH * NBINS * NPAD];
// per-roi separable weights: {g0, g1, g2, rowoff} per (ph|pw, n)
__device__ float4 g_wy[PH * NPAD];
__device__ float4 g_wx[PW * NPAD];

// ---------------------------------------------------------------------------
// Kernel 0: per-roi weight precompute. grid = (ceil(N/256), 7).
// Each thread computes BOTH the y-axis (ph=p) and x-axis (pw=p) weights for
// one roi: two INDEPENDENT dependence chains (ILP-2) and one 32B-sector read
// of all 4 coords. Halves block count vs the split-axis version (3.8 -> 1.9
// waves; the kernel is launch+latency bound, not compute bound).
// Branchless SCALAR accumulators (dynamic-index register arrays spill).
// Input bounds: rs*>=0, re*<34 -> every sample inside (-1,F), keep==true,
// count==16 (folded as 1/16 into gy), lower bilinear corner always valid.
// ---------------------------------------------------------------------------
__global__ void __launch_bounds__(TPB) weights_kernel(
    const float* __restrict__ rois, int N)
{
    const int n = blockIdx.x * TPB + threadIdx.x;
    if (n >= N) return;
    const int p = blockIdx.y;                 // 0..6
    const float fp = (float)p;

    const float rsw = __ldg(&rois[n * 5 + 1]) * 0.125f;
    const float rsh = __ldg(&rois[n * 5 + 2]) * 0.125f;
    const float rew = __ldg(&rois[n * 5 + 3]) * 0.125f;
    const float reh = __ldg(&rois[n * 5 + 4]) * 0.125f;

    float roi_h = reh - rsh; if (!(roi_h > 0.1f)) roi_h = 0.1f;
    float roi_w = rew - rsw; if (!(roi_w > 0.1f)) roi_w = 0.1f;

    const float bin_h = __fdiv_rn(roi_h, 7.0f);
    const float bin_w = __fdiv_rn(roi_w, 7.0f);
    const float sub_h = 0.25f * bin_h;
    const float sub_w = 0.25f * bin_w;

    const float hstart = floorf(__fadd_rn(rsh, __fmul_rn(fp, bin_h)));
    const float wstart = floorf(__fadd_rn(rsw, __fmul_rn(fp, bin_w)));
    const int y0 = (int)hstart;
    const int x0 = (int)wstart;

    float gy0 = 0.f, gy1 = 0.f, gy2 = 0.f;
    float gx0 = 0.f, gx1 = 0.f, gx2 = 0.f;

    #pragma unroll
    for (int s = 0; s < SP; ++s) {
        const float fs = (float)s + 0.5f;
        // Two independent chains -> ILP 2
        {
            const float P  = __fadd_rn(hstart, __fmul_rn(fs, sub_h));
            const float pf = floorf(P);
            const float d  = P - pf;
            const int v1 = (int)pf;
            const bool hi = (v1 != y0);
            const float w1 = 1.0f - d;
            const float w2 = (v1 + 1 < FH) ? d : 0.0f;
            gy0 += hi ? 0.0f : w1;
            gy1 += hi ? w1   : w2;
            gy2 += hi ? w2   : 0.0f;
        }
        {
            const float P  = __fadd_rn(wstart, __fmul_rn(fs, sub_w));
            const float pf = floorf(P);
            const float d  = P - pf;
            const int v1 = (int)pf;
            const bool hi = (v1 != x0);
            const float w1 = 1.0f - d;
            const float w2 = (v1 + 1 < FW) ? d : 0.0f;
            gx0 += hi ? 0.0f : w1;
            gx1 += hi ? w1   : w2;
            gx2 += hi ? w2   : 0.0f;
        }
    }

    g_wy[p * NPAD + n] = make_float4(gy0 * 0.0625f, gy1 * 0.0625f,
                                     gy2 * 0.0625f, (float)(y0 * FW));
    g_wx[p * NPAD + n] = make_float4(gx0, gx1, gx2, (float)x0);
}

// ---------------------------------------------------------------------------
// Kernel 1: per-bin gather into fp16 scratch (coalesced n-major STG.16).
// Feature staged as fp16 [pix][16 halves] -> 2 LDS per tap (LDS.128+LDS.32);
// psroi is LDS-crossbar-bound (proven by the R12/R13 fp16 wins).
// 2x2 core taps always live (first sample offset 0.5*sub < 1), third
// row/column branch-guarded. Accumulation stays f32.
// ---------------------------------------------------------------------------
__global__ void __launch_bounds__(TPB) psroi_kernel(
    const float* __restrict__ ft, int N)
{
    __shared__ __align__(16) __half sm[NPIX * PADC];   // 36,992 B

    const int bin = blockIdx.y;
    const int ph  = bin / PW;
    const int pw  = bin - ph * PW;
    const int tid = threadIdx.x;

    // Stage the (ph,pw) slice, all 10 channels, as fp16 [pix][c]
    {
        const float* base = ft + (size_t)bin * NPIX;
        for (int p = tid; p < NPIX; p += TPB) {
            unsigned int h2[5];
            #pragma unroll
            for (int c = 0; c < 5; ++c) {
                float a = base[(size_t)(2 * c)     * (NBINS * NPIX) + p];
                float b = base[(size_t)(2 * c + 1) * (NBINS * NPIX) + p];
                __half2 hh = __floats2half2_rn(a, b);
                h2[c] = *(unsigned int*)&hh;
            }
            uint4* dst = (uint4*)(sm + p * PADC);
            *dst = make_uint4(h2[0], h2[1], h2[2], h2[3]);
            *(unsigned int*)(sm + p * PADC + 8) = h2[4];
        }
    }
    __syncthreads();

    const float4* __restrict__ wyp = g_wy + (size_t)ph * NPAD;
    const float4* __restrict__ wxp = g_wx + (size_t)pw * NPAD;

    const int nbase = blockIdx.x * RPB + tid;

    #pragma unroll 1
    for (int r = 0; r < RPT; ++r) {
        const int n = nbase + r * TPB;
        if (n >= N) break;

        const float4 wy = __ldg(&wyp[n]);
        const float4 wx = __ldg(&wxp[n]);
        const int rowbase = (int)(wy.w + wx.w);   // y0*34 + x0, exact in f32

        float acc[CH];
        #pragma unroll
        for (int c = 0; c < CH; ++c) acc[c] = 0.f;

        auto tap = [&](int pix, float w) {
            const __half* pp = sm + pix * PADC;
            const uint4 v = *(const uint4*)pp;
            const unsigned int v4 = *(const unsigned int*)(pp + 8);
            const float2 f0 = __half22float2(*(const __half2*)&v.x);
            const float2 f1 = __half22float2(*(const __half2*)&v.y);
            const float2 f2 = __half22float2(*(const __half2*)&v.z);
            const float2 f3 = __half22float2(*(const __half2*)&v.w);
            const float2 f4 = __half22float2(*(const __half2*)&v4);
            acc[0] = fmaf(w, f0.x, acc[0]);
            acc[1] = fmaf(w, f0.y, acc[1]);
            acc[2] = fmaf(w, f1.x, acc[2]);
            acc[3] = fmaf(w, f1.y, acc[3]);
            acc[4] = fmaf(w, f2.x, acc[4]);
            acc[5] = fmaf(w, f2.y, acc[5]);
            acc[6] = fmaf(w, f3.x, acc[6]);
            acc[7] = fmaf(w, f3.y, acc[7]);
            acc[8] = fmaf(w, f4.x, acc[8]);
            acc[9] = fmaf(w, f4.y, acc[9]);
        };

        // When y0==33 (x0==33) the row1/col1 weights are provably zero, so
        // clamping keeps the dead read in-bounds. Float compares: y0<33 iff
        // rowoff(y) < 33*34 = 1122; x0<33 directly.
        const int r0 = rowbase;
        const int r1 = r0 + ((wy.w < 1122.0f) ? FW : 0);
        const int c1 = (wx.w < 33.0f) ? 1 : 0;

        // 2x2 core: always live, unconditional -> 8 LDS pipelined.
        tap(r0,      wy.x * wx.x);
        tap(r0 + c1, wy.x * wx.y);
        tap(r1,      wy.y * wx.x);
        tap(r1 + c1, wy.y * wx.y);

        if (wx.z != 0.f) {
            tap(r0 + 2, wy.x * wx.z);
            tap(r1 + 2, wy.y * wx.z);
        }
        if (wy.z != 0.f) {
            const int r2 = r0 + 2 * FW;
            tap(r2,      wy.z * wx.x);
            tap(r2 + c1, wy.z * wx.y);
            if (wx.z != 0.f)
                tap(r2 + 2, wy.z * wx.z);
        }

        __half* sc = g_scratch + (size_t)bin * NPAD + n;
        #pragma unroll
        for (int c = 0; c < CH; ++c)
            sc[(size_t)c * (NBINS * NPAD)] = __float2half_rn(acc[c]);
    }
}

// ---------------------------------------------------------------------------
// Kernel 2: out[n*490 + q] = (float)scratch[q*NPAD + n], q = c*49+bin.
// Single 32q x 128n tile per block (proven best: many small high-occupancy
// tiles). Load: one LDG.64 (4 halves = 4 n) per thread per q-row-pass,
// convert to f32, STS. Store phase: proven conflict-free f32 path.
// ---------------------------------------------------------------------------
#define TQ 32
#define TN 128
#define TS 129

__global__ void __launch_bounds__(256) transpose_kernel(
    float* __restrict__ out, int N)
{
    __shared__ float tile[TQ * TS];  // 16.5 KB

    const int tid   = threadIdx.x;
    const int qBase = blockIdx.y * TQ;
    const int nBase = blockIdx.x * TN;

    // Load: lane reads 4 consecutive n as uint2 (8B); warp covers 128 n.
    {
        const int lane = tid & 31;
        const int qrow = tid >> 5;            // 0..7
        #pragma unroll
        for (int qi = 0; qi < 4; ++qi) {
            const int q  = qrow + qi * 8;     // 0..31
            const int qg = qBase + q;
            if (qg < NQ) {
                const uint2 raw = __ldg((const uint2*)
                    (g_scratch + (size_t)qg * NPAD + nBase + lane * 4));
                const float2 a = __half22float2(*(const __half2*)&raw.x);
                const float2 b = __half22float2(*(const __half2*)&raw.y);
                float* t = tile + q * TS + lane * 4;
                t[0] = a.x; t[1] = a.y; t[2] = b.x; t[3] = b.y;
            }
        }
    }
    __syncthreads();

    // Store: half-warp covers a 128B contiguous q-span of one output row.
    {
        const int c2 = tid & 15;              // q pair: qBase + 2*c2
        const int nr = tid >> 4;              // 0..15
        const int q0 = qBase + 2 * c2;
        if (q0 + 1 < NQ) {
            #pragma unroll
            for (int k = 0; k < 8; ++k) {
                const int nl = nr + k * 16;   // 0..127
                const int ng = nBase + nl;
                if (ng < N) {
                    float2 v;
                    v.x = tile[(2 * c2)     * TS + nl];
                    v.y = tile[(2 * c2 + 1) * TS + nl];
                    *(float2*)(out + (size_t)ng * NQ + q0) = v;
                }
            }
        }
    }
}

extern "C" void kernel_launch(void* const* d_in, const int* in_sizes, int n_in,
                              void* d_out, int out_size)
{
    const float* ft   = (const float*)d_in[0];   // 490*34*34 floats
    const float* rois = (const float*)d_in[1];   // N*5 floats
    float* out        = (float*)d_out;           // N*10*49 floats

    const int N = in_sizes[1] / 5;

    dim3 grid0((N + TPB - 1) / TPB, PH);       // 7 blocks in y: both axes/thread
    weights_kernel<<<grid0, TPB>>>(rois, N);

    dim3 grid1((N + RPB - 1) / RPB, NBINS);
    psroi_kernel<<<grid1, TPB>>>(ft, N);

    dim3 grid2((N + TN - 1) / TN, (NQ + TQ - 1) / TQ);
    transpose_kernel<<<grid2, 256>>>(out, N);
}